// round 6
// baseline (speedup 1.0000x reference)
#include <cuda_runtime.h>
#include <cuda_bf16.h>
#include <cstdint>

#define Bdim 64
#define Tdim 512
#define Idim 512
#define Hdim 1024
#define Gdim 4096
#define NCTA 128

typedef unsigned long long ull;

// ---------------- device globals (allocation-free scratch) ----------------------
__device__ float g_gates_x[(size_t)Tdim * Bdim * Gdim];          // [t][b][4096]
__device__ __nv_bfloat16 g_h[2][2][Bdim][Hdim];                  // [pp][hi/lo][b][k]
__device__ __nv_bfloat16 g_W_img[NCTA][2][32][Hdim];             // [jb][hi/lo][nl][k]
__device__ float g_c[NCTA][Bdim][8];                             // cell state

// ---------------- helpers --------------------------------------------------------
__device__ __forceinline__ uint32_t smem_u32(const void* p) {
    uint32_t a;
    asm("{ .reg .u64 t; cvta.to.shared.u64 t, %1; cvt.u32.u64 %0, t; }" : "=r"(a) : "l"(p));
    return a;
}
__device__ __forceinline__ void cp16(uint32_t dst, const void* src) {
    asm volatile("cp.async.ca.shared.global [%0], [%1], 16;" :: "r"(dst), "l"(src) : "memory");
}
__device__ __forceinline__ void cp_commit() {
    asm volatile("cp.async.commit_group;" ::: "memory");
}
template <int N>
__device__ __forceinline__ void cp_wait() {
    asm volatile("cp.async.wait_group %0;" :: "n"(N) : "memory");
}
__device__ __forceinline__ void ldm_x4(uint32_t& r0, uint32_t& r1, uint32_t& r2,
                                       uint32_t& r3, uint32_t addr) {
    asm volatile("ldmatrix.sync.aligned.m8n8.x4.shared.b16 {%0,%1,%2,%3}, [%4];"
                 : "=r"(r0), "=r"(r1), "=r"(r2), "=r"(r3) : "r"(addr));
}
__device__ __forceinline__ void mma_bf16(float* c, uint32_t a0, uint32_t a1,
                                         uint32_t a2, uint32_t a3,
                                         uint32_t b0, uint32_t b1) {
    asm volatile(
        "mma.sync.aligned.m16n8k16.row.col.f32.bf16.bf16.f32 "
        "{%0,%1,%2,%3}, {%4,%5,%6,%7}, {%8,%9}, {%0,%1,%2,%3};"
        : "+f"(c[0]), "+f"(c[1]), "+f"(c[2]), "+f"(c[3])
        : "r"(a0), "r"(a1), "r"(a2), "r"(a3), "r"(b0), "r"(b1));
}
__device__ __forceinline__ ull pack2(float x, float y) {
    ull r; asm("mov.b64 %0, {%1,%2};" : "=l"(r) : "f"(x), "f"(y)); return r;
}
__device__ __forceinline__ void unpack2(ull v, float& x, float& y) {
    asm("mov.b64 {%0,%1}, %2;" : "=f"(x), "=f"(y) : "l"(v));
}
__device__ __forceinline__ void ffma2(ull& d, ull a, ull b) {
    asm("fma.rn.f32x2 %0, %1, %2, %0;" : "+l"(d) : "l"(a), "l"(b));
}
__device__ __forceinline__ float sigm_(float x) {
    return __fdividef(1.0f, 1.0f + __expf(-x));
}
__device__ __forceinline__ float tanh_(float x) {
    return 1.0f - __fdividef(2.0f, __expf(2.0f * x) + 1.0f);
}

// ---------------- init ------------------------------------------------------------
__global__ void init_state(float* __restrict__ out) {
    int i = blockIdx.x * blockDim.x + threadIdx.x;  // 65536 threads
    ((uint32_t*)g_h[0])[i] = 0u;
    ((float*)g_c)[i] = 0.0f;
    out[i] = 0.0f;
}

// ---------------- W_hh -> per-CTA bf16 hi/lo image ---------------------------------
__global__ __launch_bounds__(256) void w_prep(const float* __restrict__ Whh) {
    int bid = blockIdx.x;            // 4096 = 128 jb x 32 nl
    int jb = bid >> 5;
    int nl = bid & 31;
    int grow = (nl >> 3) * Hdim + jb * 8 + (nl & 7);
    const float* src = Whh + (size_t)grow * Hdim;
#pragma unroll
    for (int q = 0; q < 4; q++) {
        int k = q * 256 + threadIdx.x;
        float w = src[k];
        __nv_bfloat16 hi = __float2bfloat16(w);
        __nv_bfloat16 lo = __float2bfloat16(w - __bfloat162float(hi));
        g_W_img[jb][0][nl][k] = hi;
        g_W_img[jb][1][nl][k] = lo;
    }
}

// ---------------- GEMM1 (fp32x2 SIMT, round-4 layout: coalesced-ish writes) --------
__global__ __launch_bounds__(256) void gates_x_gemm(
    const float* __restrict__ seq, const float* __restrict__ Wih,
    const float* __restrict__ bih, const float* __restrict__ bhh) {
    __shared__ float As[8][132];
    __shared__ float Bs[8][132];

    const int tid = threadIdx.x;
    const int tx = tid & 15;
    const int ty = tid >> 4;
    const int m0 = blockIdx.y * 128;
    const int n0 = blockIdx.x * 128;

    const int lr = tid >> 1;
    const int lk = (tid & 1) * 4;
    const float* aptr = seq + (size_t)(m0 + lr) * Idim + lk;
    const float* bptr = Wih + (size_t)(n0 + lr) * Idim + lk;

    ull acc[8][4];
#pragma unroll
    for (int i = 0; i < 8; i++)
#pragma unroll
        for (int j = 0; j < 4; j++) acc[i][j] = 0ull;

    for (int k0 = 0; k0 < Idim; k0 += 8) {
        float4 av = *(const float4*)(aptr + k0);
        float4 bv = *(const float4*)(bptr + k0);
        As[lk + 0][lr] = av.x; As[lk + 1][lr] = av.y;
        As[lk + 2][lr] = av.z; As[lk + 3][lr] = av.w;
        Bs[lk + 0][lr] = bv.x; Bs[lk + 1][lr] = bv.y;
        Bs[lk + 2][lr] = bv.z; Bs[lk + 3][lr] = bv.w;
        __syncthreads();
#pragma unroll
        for (int k = 0; k < 8; k++) {
            float4 a0 = *(const float4*)&As[k][ty * 8];
            float4 a1 = *(const float4*)&As[k][ty * 8 + 4];
            ull pb0 = *(const ull*)&Bs[k][tx * 8 + 0];
            ull pb1 = *(const ull*)&Bs[k][tx * 8 + 2];
            ull pb2 = *(const ull*)&Bs[k][tx * 8 + 4];
            ull pb3 = *(const ull*)&Bs[k][tx * 8 + 6];
            float am[8] = {a0.x, a0.y, a0.z, a0.w, a1.x, a1.y, a1.z, a1.w};
#pragma unroll
            for (int i = 0; i < 8; i++) {
                ull pa = pack2(am[i], am[i]);
                ffma2(acc[i][0], pa, pb0);
                ffma2(acc[i][1], pa, pb1);
                ffma2(acc[i][2], pa, pb2);
                ffma2(acc[i][3], pa, pb3);
            }
        }
        __syncthreads();
    }

#pragma unroll
    for (int i = 0; i < 8; i++) {
        int m = m0 + ty * 8 + i;
        int b = m >> 9;        // T = 512
        int t = m & 511;
        float* orow = g_gates_x + (size_t)(t * Bdim + b) * Gdim;
#pragma unroll
        for (int j = 0; j < 4; j++) {
            int n = n0 + tx * 8 + j * 2;
            float x, y; unpack2(acc[i][j], x, y);
            orow[n]     = x + bih[n]     + bhh[n];
            orow[n + 1] = y + bih[n + 1] + bhh[n + 1];
        }
    }
}

// ---------------- per-step HMMA kernel ---------------------------------------------
// 128 CTAs x 512 thr (16 warps). CTA jb: gates[64 x 32] = h[64x1024] @ Wslice^T,
// split-bf16 (3 terms, 3 independent accumulators). K chunked x128,
// 4-stage cp.async ring, ONE __syncthreads per chunk (issue-after-sync ordering).
// Warp w: mt = w&3 (rows mt*16..), nq = w>>2 (cols nq*8..) -> one m16n8 output.
#define KC 128
#define NCHUNK 8
#define PITCH 272           // 128 bf16 = 256B + 16B pad per row
#define HPLANE (64 * PITCH) // 17408
#define HBUF (2 * HPLANE)   // 34816
#define WPLANE (32 * PITCH) // 8704
#define WBUF (2 * WPLANE)   // 17408
#define SBUF (HBUF + WBUF)  // 52224
#define OFF_PRE (4 * SBUF)  // 208896
#define SMEM_BYTES (OFF_PRE + 64 * 36 * 4)  // 218112

__global__ __launch_bounds__(512) void lstm_step_mma(
    const int* __restrict__ lens, float* __restrict__ out, int t) {
    extern __shared__ unsigned char smem[];
    const uint32_t sb = smem_u32(smem);
    float* pre = (float*)(smem + OFF_PRE);  // [64][36]

    const int tid = threadIdx.x;
    const int lane = tid & 31;
    const int w = tid >> 5;
    const int jb = blockIdx.x;
    const int j0 = jb * 8;
    const int pp = t & 1;

    // ---- early prefetch for the pointwise tail (threads 0-63, b = tid)
    float gxi[8], gxf[8], gxg[8], gxo[8], cst[8];
    int lb = 0;
    if (tid < 64) {
        const float* gxb = g_gates_x + ((size_t)t * Bdim + tid) * Gdim + j0;
#pragma unroll
        for (int g = 0; g < 4; g++) {
            float4 v0 = *(const float4*)(gxb + g * Hdim);
            float4 v1 = *(const float4*)(gxb + g * Hdim + 4);
            float* dstp = (g == 0) ? gxi : (g == 1) ? gxf : (g == 2) ? gxg : gxo;
            dstp[0] = v0.x; dstp[1] = v0.y; dstp[2] = v0.z; dstp[3] = v0.w;
            dstp[4] = v1.x; dstp[5] = v1.y; dstp[6] = v1.z; dstp[7] = v1.w;
        }
        float4 c0 = *(const float4*)&g_c[jb][tid][0];
        float4 c1 = *(const float4*)&g_c[jb][tid][4];
        cst[0] = c0.x; cst[1] = c0.y; cst[2] = c0.z; cst[3] = c0.w;
        cst[4] = c1.x; cst[5] = c1.y; cst[6] = c1.z; cst[7] = c1.w;
        lb = lens[tid];
    }

    // ---- per-lane ldmatrix offsets
    const int mt = w & 3;
    const int nq = w >> 2;
    const uint32_t a_off = (uint32_t)((mt * 16 + (lane & 7) + ((lane >> 3) & 1) * 8) * PITCH
                                      + ((lane >> 4) & 1) * 16);
    // B x4 spanning 2 k-slices: matrices {ks:k0-7, ks:k8-15, ks+1:k0-7, ks+1:k8-15}
    const uint32_t b_off = (uint32_t)((nq * 8 + (lane & 7)) * PITCH + ((lane >> 3) & 3) * 16);

    float C0[4] = {0.f, 0.f, 0.f, 0.f};   // Ah*Bh
    float C1[4] = {0.f, 0.f, 0.f, 0.f};   // Ah*Bl
    float C2[4] = {0.f, 0.f, 0.f, 0.f};   // Al*Bh

    const __nv_bfloat16* hsrc = &g_h[pp][0][0][0];
    const __nv_bfloat16* wsrc = &g_W_img[jb][0][0][0];

    auto issue_chunk = [&](int kc) {
        uint32_t base = sb + (kc & 3) * SBUF;
#pragma unroll
        for (int q = 0; q < 4; q++) {       // h: 2048 x 16B ops
            int i = q * 512 + tid;
            int seg = i & 15;
            int rp = i >> 4;                // 0..127
            int plane = rp >> 6, b = rp & 63;
            const void* src = hsrc + ((size_t)plane * Bdim + b) * Hdim + kc * KC + seg * 8;
            cp16(base + plane * HPLANE + b * PITCH + seg * 16, src);
        }
#pragma unroll
        for (int q = 0; q < 2; q++) {       // w: 1024 x 16B ops
            int i = q * 512 + tid;
            int seg = i & 15;
            int rp = i >> 4;                // 0..63
            int plane = rp >> 5, nl = rp & 31;
            const void* src = wsrc + ((size_t)plane * 32 + nl) * Hdim + kc * KC + seg * 8;
            cp16(base + HBUF + plane * WPLANE + nl * PITCH + seg * 16, src);
        }
        cp_commit();
    };

    issue_chunk(0);
    issue_chunk(1);
    issue_chunk(2);

    for (int kc = 0; kc < NCHUNK; kc++) {
        if (kc + 3 < NCHUNK)      { cp_wait<2>(); }
        else if (kc + 2 < NCHUNK) { cp_wait<2>(); }
        else if (kc + 1 < NCHUNK) { cp_wait<1>(); }
        else                      { cp_wait<0>(); }
        __syncthreads();
        // safe: buffer (kc+3)&3 was last read in iteration kc-1, retired by the sync
        if (kc + 3 < NCHUNK) issue_chunk(kc + 3);

        uint32_t base = sb + (kc & 3) * SBUF;
        uint32_t ha = base + a_off;
        uint32_t wa = base + HBUF + b_off;
#pragma unroll
        for (int ks2 = 0; ks2 < KC / 32; ks2++) {
            uint32_t bh0, bh1, bh2, bh3, bl0, bl1, bl2, bl3;
            ldm_x4(bh0, bh1, bh2, bh3, wa + ks2 * 64);
            ldm_x4(bl0, bl1, bl2, bl3, wa + WPLANE + ks2 * 64);
            {
                uint32_t ah0, ah1, ah2, ah3, al0, al1, al2, al3;
                ldm_x4(ah0, ah1, ah2, ah3, ha + ks2 * 64);
                ldm_x4(al0, al1, al2, al3, ha + HPLANE + ks2 * 64);
                mma_bf16(C0, ah0, ah1, ah2, ah3, bh0, bh1);
                mma_bf16(C1, ah0, ah1, ah2, ah3, bl0, bl1);
                mma_bf16(C2, al0, al1, al2, al3, bh0, bh1);
            }
            {
                uint32_t ah0, ah1, ah2, ah3, al0, al1, al2, al3;
                ldm_x4(ah0, ah1, ah2, ah3, ha + ks2 * 64 + 32);
                ldm_x4(al0, al1, al2, al3, ha + HPLANE + ks2 * 64 + 32);
                mma_bf16(C0, ah0, ah1, ah2, ah3, bh2, bh3);
                mma_bf16(C1, ah0, ah1, ah2, ah3, bl2, bl3);
                mma_bf16(C2, al0, al1, al2, al3, bh2, bh3);
            }
        }
    }
    __syncthreads();

    // merge split terms and stage to pre[64][36]
    {
        float Cs[4];
#pragma unroll
        for (int q = 0; q < 4; q++) Cs[q] = C0[q] + C1[q] + C2[q];
        int g = lane >> 2, t2 = (lane & 3) * 2;
        int m = mt * 16 + g;
        int n = nq * 8 + t2;
        *(float2*)&pre[m * 36 + n]       = make_float2(Cs[0], Cs[1]);
        *(float2*)&pre[(m + 8) * 36 + n] = make_float2(Cs[2], Cs[3]);
    }
    __syncthreads();

    // pointwise LSTM cell (threads 0-63, b = tid)
    if (tid < 64) {
        int b = tid;
        float hn[8];
        unsigned short hu[8], lu[8];
#pragma unroll
        for (int jj = 0; jj < 8; jj++) {
            float xi = pre[b * 36 + jj]      + gxi[jj];
            float xf = pre[b * 36 + 8 + jj]  + gxf[jj];
            float xg = pre[b * 36 + 16 + jj] + gxg[jj];
            float xo = pre[b * 36 + 24 + jj] + gxo[jj];
            float i_ = sigm_(xi), f_ = sigm_(xf), g_ = tanh_(xg), o_ = sigm_(xo);
            float cn = f_ * cst[jj] + i_ * g_;
            cst[jj] = cn;
            float h = o_ * tanh_(cn);
            hn[jj] = h;
            __nv_bfloat16 hh = __float2bfloat16(h);
            __nv_bfloat16 hl = __float2bfloat16(h - __bfloat162float(hh));
            hu[jj] = __bfloat16_as_ushort(hh);
            lu[jj] = __bfloat16_as_ushort(hl);
        }
        *(float4*)&g_c[jb][b][0] = make_float4(cst[0], cst[1], cst[2], cst[3]);
        *(float4*)&g_c[jb][b][4] = make_float4(cst[4], cst[5], cst[6], cst[7]);

        uint4 vh, vl;
        vh.x = (uint32_t)hu[0] | ((uint32_t)hu[1] << 16);
        vh.y = (uint32_t)hu[2] | ((uint32_t)hu[3] << 16);
        vh.z = (uint32_t)hu[4] | ((uint32_t)hu[5] << 16);
        vh.w = (uint32_t)hu[6] | ((uint32_t)hu[7] << 16);
        vl.x = (uint32_t)lu[0] | ((uint32_t)lu[1] << 16);
        vl.y = (uint32_t)lu[2] | ((uint32_t)lu[3] << 16);
        vl.z = (uint32_t)lu[4] | ((uint32_t)lu[5] << 16);
        vl.w = (uint32_t)lu[6] | ((uint32_t)lu[7] << 16);
        int pp1 = (t + 1) & 1;
        *(uint4*)&g_h[pp1][0][b][j0] = vh;
        *(uint4*)&g_h[pp1][1][b][j0] = vl;

        if (lb > t) {
            float* ob = out + (size_t)b * Hdim + j0;
            *(float4*)(ob)     = make_float4(hn[0], hn[1], hn[2], hn[3]);
            *(float4*)(ob + 4) = make_float4(hn[4], hn[5], hn[6], hn[7]);
        }
    }
}

// ---------------- launch ------------------------------------------------------------
extern "C" void kernel_launch(void* const* d_in, const int* in_sizes, int n_in,
                              void* d_out, int out_size) {
    const float* seq   = (const float*)d_in[0];
    const int*   lensp = (const int*)d_in[1];
    const float* Wih   = (const float*)d_in[2];
    const float* Whh   = (const float*)d_in[3];
    const float* bih   = (const float*)d_in[4];
    const float* bhh   = (const float*)d_in[5];
    float* out = (float*)d_out;

    cudaFuncSetAttribute(lstm_step_mma,
                         cudaFuncAttributeMaxDynamicSharedMemorySize, SMEM_BYTES);

    init_state<<<256, 256>>>(out);
    w_prep<<<4096, 256>>>(Whh);

    dim3 g1(Gdim / 128, (Bdim * Tdim) / 128);
    gates_x_gemm<<<g1, 256>>>(seq, Wih, bih, bhh);

    for (int t = 0; t < Tdim; t++) {
        lstm_step_mma<<<NCTA, 512, SMEM_BYTES>>>(lensp, out, t);
    }
}

// round 7
// speedup vs baseline: 1.0311x; 1.0311x over previous
#include <cuda_runtime.h>
#include <cuda_bf16.h>
#include <cstdint>

#define Bdim 64
#define Tdim 512
#define Idim 512
#define Hdim 1024
#define Gdim 4096
#define NCTA 128

typedef unsigned long long ull;

// ---------------- device globals (allocation-free scratch) ----------------------
__device__ float g_gates_x[(size_t)Tdim * Bdim * Gdim];          // [t][b][4096]
__device__ __nv_bfloat16 g_h[2][2][Bdim][Hdim];                  // [pp][hi/lo][b][k]
__device__ unsigned g_bar_cnt;

// ---------------- helpers --------------------------------------------------------
__device__ __forceinline__ uint32_t smem_u32(const void* p) {
    uint32_t a;
    asm("{ .reg .u64 t; cvta.to.shared.u64 t, %1; cvt.u32.u64 %0, t; }" : "=r"(a) : "l"(p));
    return a;
}
__device__ __forceinline__ void cp16(uint32_t dst, const void* src) {
    asm volatile("cp.async.ca.shared.global [%0], [%1], 16;" :: "r"(dst), "l"(src) : "memory");
}
__device__ __forceinline__ void cp_commit() {
    asm volatile("cp.async.commit_group;" ::: "memory");
}
template <int N>
__device__ __forceinline__ void cp_wait() {
    asm volatile("cp.async.wait_group %0;" :: "n"(N) : "memory");
}
__device__ __forceinline__ void ldm_x4(uint32_t& r0, uint32_t& r1, uint32_t& r2,
                                       uint32_t& r3, uint32_t addr) {
    asm volatile("ldmatrix.sync.aligned.m8n8.x4.shared.b16 {%0,%1,%2,%3}, [%4];"
                 : "=r"(r0), "=r"(r1), "=r"(r2), "=r"(r3) : "r"(addr));
}
__device__ __forceinline__ void ldm_x2(uint32_t& r0, uint32_t& r1, uint32_t addr) {
    asm volatile("ldmatrix.sync.aligned.m8n8.x2.shared.b16 {%0,%1}, [%2];"
                 : "=r"(r0), "=r"(r1) : "r"(addr));
}
__device__ __forceinline__ void mma_bf16(float* c, uint32_t a0, uint32_t a1,
                                         uint32_t a2, uint32_t a3,
                                         uint32_t b0, uint32_t b1) {
    asm volatile(
        "mma.sync.aligned.m16n8k16.row.col.f32.bf16.bf16.f32 "
        "{%0,%1,%2,%3}, {%4,%5,%6,%7}, {%8,%9}, {%0,%1,%2,%3};"
        : "+f"(c[0]), "+f"(c[1]), "+f"(c[2]), "+f"(c[3])
        : "r"(a0), "r"(a1), "r"(a2), "r"(a3), "r"(b0), "r"(b1));
}
__device__ __forceinline__ ull pack2(float x, float y) {
    ull r; asm("mov.b64 %0, {%1,%2};" : "=l"(r) : "f"(x), "f"(y)); return r;
}
__device__ __forceinline__ void unpack2(ull v, float& x, float& y) {
    asm("mov.b64 {%0,%1}, %2;" : "=f"(x), "=f"(y) : "l"(v));
}
__device__ __forceinline__ void ffma2(ull& d, ull a, ull b) {
    asm("fma.rn.f32x2 %0, %1, %2, %0;" : "+l"(d) : "l"(a), "l"(b));
}
__device__ __forceinline__ float sigm_(float x) {
    return __fdividef(1.0f, 1.0f + __expf(-x));
}
__device__ __forceinline__ float tanh_(float x) {
    return 1.0f - __fdividef(2.0f, __expf(2.0f * x) + 1.0f);
}

// ---------------- init ------------------------------------------------------------
__global__ void init_state(float* __restrict__ out) {
    int i = blockIdx.x * blockDim.x + threadIdx.x;  // 65536 threads
    ((uint32_t*)g_h[0])[i] = 0u;   // zero both planes of pp=0 (256 KB)
    out[i] = 0.0f;
    if (i == 0) g_bar_cnt = 0u;
}

// ---------------- GEMM1 (fp32x2 SIMT, round-4 proven) -------------------------------
__global__ __launch_bounds__(256) void gates_x_gemm(
    const float* __restrict__ seq, const float* __restrict__ Wih,
    const float* __restrict__ bih, const float* __restrict__ bhh) {
    __shared__ float As[8][132];
    __shared__ float Bs[8][132];

    const int tid = threadIdx.x;
    const int tx = tid & 15;
    const int ty = tid >> 4;
    const int m0 = blockIdx.y * 128;
    const int n0 = blockIdx.x * 128;

    const int lr = tid >> 1;
    const int lk = (tid & 1) * 4;
    const float* aptr = seq + (size_t)(m0 + lr) * Idim + lk;
    const float* bptr = Wih + (size_t)(n0 + lr) * Idim + lk;

    ull acc[8][4];
#pragma unroll
    for (int i = 0; i < 8; i++)
#pragma unroll
        for (int j = 0; j < 4; j++) acc[i][j] = 0ull;

    for (int k0 = 0; k0 < Idim; k0 += 8) {
        float4 av = *(const float4*)(aptr + k0);
        float4 bv = *(const float4*)(bptr + k0);
        As[lk + 0][lr] = av.x; As[lk + 1][lr] = av.y;
        As[lk + 2][lr] = av.z; As[lk + 3][lr] = av.w;
        Bs[lk + 0][lr] = bv.x; Bs[lk + 1][lr] = bv.y;
        Bs[lk + 2][lr] = bv.z; Bs[lk + 3][lr] = bv.w;
        __syncthreads();
#pragma unroll
        for (int k = 0; k < 8; k++) {
            float4 a0 = *(const float4*)&As[k][ty * 8];
            float4 a1 = *(const float4*)&As[k][ty * 8 + 4];
            ull pb0 = *(const ull*)&Bs[k][tx * 8 + 0];
            ull pb1 = *(const ull*)&Bs[k][tx * 8 + 2];
            ull pb2 = *(const ull*)&Bs[k][tx * 8 + 4];
            ull pb3 = *(const ull*)&Bs[k][tx * 8 + 6];
            float am[8] = {a0.x, a0.y, a0.z, a0.w, a1.x, a1.y, a1.z, a1.w};
#pragma unroll
            for (int i = 0; i < 8; i++) {
                ull pa = pack2(am[i], am[i]);
                ffma2(acc[i][0], pa, pb0);
                ffma2(acc[i][1], pa, pb1);
                ffma2(acc[i][2], pa, pb2);
                ffma2(acc[i][3], pa, pb3);
            }
        }
        __syncthreads();
    }

#pragma unroll
    for (int i = 0; i < 8; i++) {
        int m = m0 + ty * 8 + i;
        int b = m >> 9;        // T = 512
        int t = m & 511;
        float* orow = g_gates_x + (size_t)(t * Bdim + b) * Gdim;
#pragma unroll
        for (int j = 0; j < 4; j++) {
            int n = n0 + tx * 8 + j * 2;
            float x, y; unpack2(acc[i][j], x, y);
            orow[n]     = x + bih[n]     + bhh[n];
            orow[n + 1] = y + bih[n + 1] + bhh[n + 1];
        }
    }
}

// ---------------- persistent HMMA recurrence kernel ---------------------------------
// 128 CTAs (1/SM, smem 214 KB) x 512 thr (16 warps). CTA jb owns hidden cols
// [jb*8, jb*8+8) -> 32 gate rows. W_hh slice (bf16 hi/lo) RESIDENT in smem for all
// 512 steps. c-state in registers. h ping-pongs via global; spin grid barrier/step.
// Warp w: mt = w&3 (rows mt*16..), nq = w>>2 (cols nq*8..) -> one m16n8 output.
#define KC 128
#define NCHUNK 8
#define W_PITCH 2064                 // 1024 bf16 = 2048 B + 16 pad (ldm conflict-free)
#define W_PLANE (32 * W_PITCH)       // 66048
#define OFF_W 0
#define H_PITCH 272                  // 128 bf16 = 256 B + 16 pad
#define H_PLANE (64 * H_PITCH)       // 17408
#define H_BUF (2 * H_PLANE)          // 34816
#define OFF_H (2 * W_PLANE)          // 132096
#define OFF_GX (OFF_H + 2 * H_BUF)   // 201728 (64 x 32 floats)
#define OFF_PRE (OFF_GX + 64 * 32 * 4)  // 209920 (64 x 36 floats)
#define SMEM_BYTES (OFF_PRE + 64 * 36 * 4)  // 219136

__global__ __launch_bounds__(512, 1) void lstm_persist(
    const float* __restrict__ Whh, const int* __restrict__ lens,
    float* __restrict__ out) {
    extern __shared__ unsigned char smem[];
    const uint32_t sb = smem_u32(smem);
    float* gxs = (float*)(smem + OFF_GX);   // [64][32]
    float* pre = (float*)(smem + OFF_PRE);  // [64][36]

    const int tid = threadIdx.x;
    const int lane = tid & 31;
    const int w = tid >> 5;
    const int jb = blockIdx.x;
    const int j0 = jb * 8;

    // ---- one-time: W_hh slice -> smem bf16 hi/lo (32 rows x 1024 k)
    for (int idx = tid; idx < 32 * Hdim; idx += 512) {
        int nl = idx >> 10;
        int k = idx & 1023;
        int grow = (nl >> 3) * Hdim + j0 + (nl & 7);
        float v = Whh[(size_t)grow * Hdim + k];
        __nv_bfloat16 hi = __float2bfloat16(v);
        __nv_bfloat16 lo = __float2bfloat16(v - __bfloat162float(hi));
        *(__nv_bfloat16*)(smem + OFF_W + nl * W_PITCH + k * 2) = hi;
        *(__nv_bfloat16*)(smem + OFF_W + W_PLANE + nl * W_PITCH + k * 2) = lo;
    }
    __syncthreads();

    // ---- per-lane ldmatrix offsets (fragment layout proven in rounds 4-5)
    const int mt = w & 3;
    const int nq = w >> 2;
    const uint32_t a_off = (uint32_t)((mt * 16 + (lane & 7) + ((lane >> 3) & 1) * 8) * H_PITCH
                                      + ((lane >> 4) & 1) * 16);
    const int l16 = lane & 15;
    const uint32_t wb_off = sb + OFF_W +
        (uint32_t)((nq * 8 + (l16 & 7)) * W_PITCH + ((l16 >> 3) & 1) * 16);

    // ---- persistent per-thread state (threads 0-63: b = tid)
    float cst[8];
#pragma unroll
    for (int q = 0; q < 8; q++) cst[q] = 0.0f;
    const int lb = (tid < 64) ? lens[tid] : 0;

    for (int t = 0; t < Tdim; t++) {
        const int pp = t & 1;
        const __nv_bfloat16* hsrc = &g_h[pp][0][0][0];

        // h-chunk copy issuer (all 512 threads, 4 x 16B each)
        auto issue_chunk = [&](int kc) {
            uint32_t base = sb + OFF_H + (kc & 1) * H_BUF;
#pragma unroll
            for (int q = 0; q < 4; q++) {
                int i = q * 512 + tid;
                int seg = i & 15;
                int rp = i >> 4;            // 0..127
                int plane = rp >> 6, b = rp & 63;
                const void* src = hsrc + ((size_t)plane * Bdim + b) * Hdim + kc * KC + seg * 8;
                cp16(base + plane * H_PLANE + b * H_PITCH + seg * 16, src);
            }
            cp_commit();
        };

        issue_chunk(0);

        // gates_x prefetch -> smem (threads 0-63, b = tid)
        if (tid < 64) {
            const float* gxb = g_gates_x + ((size_t)t * Bdim + tid) * Gdim + j0;
#pragma unroll
            for (int g = 0; g < 4; g++) {
                float4 v0 = *(const float4*)(gxb + g * Hdim);
                float4 v1 = *(const float4*)(gxb + g * Hdim + 4);
                *(float4*)&gxs[tid * 32 + g * 8]     = v0;
                *(float4*)&gxs[tid * 32 + g * 8 + 4] = v1;
            }
        }

        float C0[4] = {0.f, 0.f, 0.f, 0.f};
        float C1[4] = {0.f, 0.f, 0.f, 0.f};
        float C2[4] = {0.f, 0.f, 0.f, 0.f};

        for (int kc = 0; kc < NCHUNK; kc++) {
            if (kc + 1 < NCHUNK) { issue_chunk(kc + 1); cp_wait<1>(); }
            else                 { cp_wait<0>(); }
            __syncthreads();

            uint32_t ha = sb + OFF_H + (kc & 1) * H_BUF + a_off;
#pragma unroll
            for (int ks = 0; ks < KC / 16; ks++) {
                uint32_t ah0, ah1, ah2, ah3, al0, al1, al2, al3;
                uint32_t bh0, bh1, bl0, bl1;
                uint32_t wadr = wb_off + (kc * 8 + ks) * 32;
                ldm_x4(ah0, ah1, ah2, ah3, ha + ks * 32);
                ldm_x4(al0, al1, al2, al3, ha + H_PLANE + ks * 32);
                ldm_x2(bh0, bh1, wadr);
                ldm_x2(bl0, bl1, wadr + W_PLANE);
                mma_bf16(C0, ah0, ah1, ah2, ah3, bh0, bh1);
                mma_bf16(C1, ah0, ah1, ah2, ah3, bl0, bl1);
                mma_bf16(C2, al0, al1, al2, al3, bh0, bh1);
            }
            __syncthreads();
        }

        // merge split terms -> pre[64][36]
        {
            float Cs[4];
#pragma unroll
            for (int q = 0; q < 4; q++) Cs[q] = C0[q] + C1[q] + C2[q];
            int g = lane >> 2, t2 = (lane & 3) * 2;
            int m = mt * 16 + g;
            int n = nq * 8 + t2;
            *(float2*)&pre[m * 36 + n]       = make_float2(Cs[0], Cs[1]);
            *(float2*)&pre[(m + 8) * 36 + n] = make_float2(Cs[2], Cs[3]);
        }
        __syncthreads();

        // pointwise LSTM cell (threads 0-63, b = tid)
        if (tid < 64) {
            int b = tid;
            float hn[8];
            unsigned short hu[8], lu[8];
#pragma unroll
            for (int jj = 0; jj < 8; jj++) {
                float xi = pre[b * 36 + jj]      + gxs[b * 32 + jj];
                float xf = pre[b * 36 + 8 + jj]  + gxs[b * 32 + 8 + jj];
                float xg = pre[b * 36 + 16 + jj] + gxs[b * 32 + 16 + jj];
                float xo = pre[b * 36 + 24 + jj] + gxs[b * 32 + 24 + jj];
                float i_ = sigm_(xi), f_ = sigm_(xf), g_ = tanh_(xg), o_ = sigm_(xo);
                float cn = f_ * cst[jj] + i_ * g_;
                cst[jj] = cn;
                float h = o_ * tanh_(cn);
                hn[jj] = h;
                __nv_bfloat16 hh = __float2bfloat16(h);
                __nv_bfloat16 hl = __float2bfloat16(h - __bfloat162float(hh));
                hu[jj] = __bfloat16_as_ushort(hh);
                lu[jj] = __bfloat16_as_ushort(hl);
            }
            uint4 vh, vl;
            vh.x = (uint32_t)hu[0] | ((uint32_t)hu[1] << 16);
            vh.y = (uint32_t)hu[2] | ((uint32_t)hu[3] << 16);
            vh.z = (uint32_t)hu[4] | ((uint32_t)hu[5] << 16);
            vh.w = (uint32_t)hu[6] | ((uint32_t)hu[7] << 16);
            vl.x = (uint32_t)lu[0] | ((uint32_t)lu[1] << 16);
            vl.y = (uint32_t)lu[2] | ((uint32_t)lu[3] << 16);
            vl.z = (uint32_t)lu[4] | ((uint32_t)lu[5] << 16);
            vl.w = (uint32_t)lu[6] | ((uint32_t)lu[7] << 16);
            int pp1 = pp ^ 1;
            *(uint4*)&g_h[pp1][0][b][j0] = vh;
            *(uint4*)&g_h[pp1][1][b][j0] = vl;

            if (lb > t) {
                float* ob = out + (size_t)b * Hdim + j0;
                *(float4*)(ob)     = make_float4(hn[0], hn[1], hn[2], hn[3]);
                *(float4*)(ob + 4) = make_float4(hn[4], hn[5], hn[6], hn[7]);
            }
        }

        // grid barrier (release h writes, acquire peers')
        __syncthreads();
        if (tid == 0) {
            __threadfence();
            atomicAdd(&g_bar_cnt, 1u);
            unsigned target = (unsigned)(t + 1) * (unsigned)NCTA;
            while (*(volatile unsigned*)&g_bar_cnt < target) { }
            __threadfence();
        }
        __syncthreads();
    }
}

// ---------------- launch ------------------------------------------------------------
extern "C" void kernel_launch(void* const* d_in, const int* in_sizes, int n_in,
                              void* d_out, int out_size) {
    const float* seq   = (const float*)d_in[0];
    const int*   lensp = (const int*)d_in[1];
    const float* Wih   = (const float*)d_in[2];
    const float* Whh   = (const float*)d_in[3];
    const float* bih   = (const float*)d_in[4];
    const float* bhh   = (const float*)d_in[5];
    float* out = (float*)d_out;

    cudaFuncSetAttribute(lstm_persist,
                         cudaFuncAttributeMaxDynamicSharedMemorySize, SMEM_BYTES);

    init_state<<<256, 256>>>(out);

    dim3 g1(Gdim / 128, (Bdim * Tdim) / 128);
    gates_x_gemm<<<g1, 256>>>(seq, Wih, bih, bhh);

    lstm_persist<<<NCTA, 512, SMEM_BYTES>>>(Whh, lensp, out);
}

// round 8
// speedup vs baseline: 1.2180x; 1.1813x over previous
#include <cuda_runtime.h>
#include <cuda_bf16.h>
#include <cstdint>

#define Bdim 64
#define Tdim 512
#define Idim 512
#define Hdim 1024
#define Gdim 4096
#define NCTA 128

typedef unsigned long long ull;

// ---------------- device globals (allocation-free scratch) ----------------------
__device__ float g_gates_x[(size_t)Tdim * Bdim * Gdim];          // [t][b][4096]
__device__ __nv_bfloat16 g_h[2][2][Bdim][Hdim];                  // [pp][hi/lo][b][k]
__device__ __nv_bfloat16 g_W_img[NCTA][2][32][Hdim];             // [jb][hi/lo][nl][k]
__device__ float g_c[NCTA][Bdim][8];                             // cell state

// ---------------- helpers --------------------------------------------------------
__device__ __forceinline__ uint32_t smem_u32(const void* p) {
    uint32_t a;
    asm("{ .reg .u64 t; cvta.to.shared.u64 t, %1; cvt.u32.u64 %0, t; }" : "=r"(a) : "l"(p));
    return a;
}
__device__ __forceinline__ void cp16(uint32_t dst, const void* src) {
    asm volatile("cp.async.ca.shared.global [%0], [%1], 16;" :: "r"(dst), "l"(src) : "memory");
}
__device__ __forceinline__ void cp_commit() {
    asm volatile("cp.async.commit_group;" ::: "memory");
}
template <int N>
__device__ __forceinline__ void cp_wait() {
    asm volatile("cp.async.wait_group %0;" :: "n"(N) : "memory");
}
__device__ __forceinline__ void barq(int id) {
    asm volatile("bar.sync %0, 128;" :: "r"(id) : "memory");
}
__device__ __forceinline__ void ldm_x4(uint32_t& r0, uint32_t& r1, uint32_t& r2,
                                       uint32_t& r3, uint32_t addr) {
    asm volatile("ldmatrix.sync.aligned.m8n8.x4.shared.b16 {%0,%1,%2,%3}, [%4];"
                 : "=r"(r0), "=r"(r1), "=r"(r2), "=r"(r3) : "r"(addr));
}
__device__ __forceinline__ void mma_bf16(float* c, uint32_t a0, uint32_t a1,
                                         uint32_t a2, uint32_t a3,
                                         uint32_t b0, uint32_t b1) {
    asm volatile(
        "mma.sync.aligned.m16n8k16.row.col.f32.bf16.bf16.f32 "
        "{%0,%1,%2,%3}, {%4,%5,%6,%7}, {%8,%9}, {%0,%1,%2,%3};"
        : "+f"(c[0]), "+f"(c[1]), "+f"(c[2]), "+f"(c[3])
        : "r"(a0), "r"(a1), "r"(a2), "r"(a3), "r"(b0), "r"(b1));
}
__device__ __forceinline__ ull pack2(float x, float y) {
    ull r; asm("mov.b64 %0, {%1,%2};" : "=l"(r) : "f"(x), "f"(y)); return r;
}
__device__ __forceinline__ void unpack2(ull v, float& x, float& y) {
    asm("mov.b64 {%0,%1}, %2;" : "=f"(x), "=f"(y) : "l"(v));
}
__device__ __forceinline__ void ffma2(ull& d, ull a, ull b) {
    asm("fma.rn.f32x2 %0, %1, %2, %0;" : "+l"(d) : "l"(a), "l"(b));
}
__device__ __forceinline__ float sigm_(float x) {
    return __fdividef(1.0f, 1.0f + __expf(-x));
}
__device__ __forceinline__ float tanh_(float x) {
    return 1.0f - __fdividef(2.0f, __expf(2.0f * x) + 1.0f);
}

// ---------------- init ------------------------------------------------------------
__global__ void init_state(float* __restrict__ out) {
    int i = blockIdx.x * blockDim.x + threadIdx.x;  // 65536 threads
    ((uint32_t*)g_h[0])[i] = 0u;
    ((float*)g_c)[i] = 0.0f;
    out[i] = 0.0f;
}

// ---------------- W_hh -> per-CTA bf16 hi/lo image ---------------------------------
__global__ __launch_bounds__(256) void w_prep(const float* __restrict__ Whh) {
    int bid = blockIdx.x;            // 4096 = 128 jb x 32 nl
    int jb = bid >> 5;
    int nl = bid & 31;
    int grow = (nl >> 3) * Hdim + jb * 8 + (nl & 7);
    const float* src = Whh + (size_t)grow * Hdim;
#pragma unroll
    for (int q = 0; q < 4; q++) {
        int k = q * 256 + threadIdx.x;
        float w = src[k];
        __nv_bfloat16 hi = __float2bfloat16(w);
        __nv_bfloat16 lo = __float2bfloat16(w - __bfloat162float(hi));
        g_W_img[jb][0][nl][k] = hi;
        g_W_img[jb][1][nl][k] = lo;
    }
}

// ---------------- GEMM1 (fp32x2 SIMT, round-4 proven) -------------------------------
__global__ __launch_bounds__(256) void gates_x_gemm(
    const float* __restrict__ seq, const float* __restrict__ Wih,
    const float* __restrict__ bih, const float* __restrict__ bhh) {
    __shared__ float As[8][132];
    __shared__ float Bs[8][132];

    const int tid = threadIdx.x;
    const int tx = tid & 15;
    const int ty = tid >> 4;
    const int m0 = blockIdx.y * 128;
    const int n0 = blockIdx.x * 128;

    const int lr = tid >> 1;
    const int lk = (tid & 1) * 4;
    const float* aptr = seq + (size_t)(m0 + lr) * Idim + lk;
    const float* bptr = Wih + (size_t)(n0 + lr) * Idim + lk;

    ull acc[8][4];
#pragma unroll
    for (int i = 0; i < 8; i++)
#pragma unroll
        for (int j = 0; j < 4; j++) acc[i][j] = 0ull;

    for (int k0 = 0; k0 < Idim; k0 += 8) {
        float4 av = *(const float4*)(aptr + k0);
        float4 bv = *(const float4*)(bptr + k0);
        As[lk + 0][lr] = av.x; As[lk + 1][lr] = av.y;
        As[lk + 2][lr] = av.z; As[lk + 3][lr] = av.w;
        Bs[lk + 0][lr] = bv.x; Bs[lk + 1][lr] = bv.y;
        Bs[lk + 2][lr] = bv.z; Bs[lk + 3][lr] = bv.w;
        __syncthreads();
#pragma unroll
        for (int k = 0; k < 8; k++) {
            float4 a0 = *(const float4*)&As[k][ty * 8];
            float4 a1 = *(const float4*)&As[k][ty * 8 + 4];
            ull pb0 = *(const ull*)&Bs[k][tx * 8 + 0];
            ull pb1 = *(const ull*)&Bs[k][tx * 8 + 2];
            ull pb2 = *(const ull*)&Bs[k][tx * 8 + 4];
            ull pb3 = *(const ull*)&Bs[k][tx * 8 + 6];
            float am[8] = {a0.x, a0.y, a0.z, a0.w, a1.x, a1.y, a1.z, a1.w};
#pragma unroll
            for (int i = 0; i < 8; i++) {
                ull pa = pack2(am[i], am[i]);
                ffma2(acc[i][0], pa, pb0);
                ffma2(acc[i][1], pa, pb1);
                ffma2(acc[i][2], pa, pb2);
                ffma2(acc[i][3], pa, pb3);
            }
        }
        __syncthreads();
    }

#pragma unroll
    for (int i = 0; i < 8; i++) {
        int m = m0 + ty * 8 + i;
        int b = m >> 9;        // T = 512
        int t = m & 511;
        float* orow = g_gates_x + (size_t)(t * Bdim + b) * Gdim;
#pragma unroll
        for (int j = 0; j < 4; j++) {
            int n = n0 + tx * 8 + j * 2;
            float x, y; unpack2(acc[i][j], x, y);
            orow[n]     = x + bih[n]     + bhh[n];
            orow[n + 1] = y + bih[n + 1] + bhh[n + 1];
        }
    }
}

// ---------------- per-step HMMA kernel (wide warp-tiles, dual K pipelines) ----------
// 128 CTAs x 256 thr (8 warps). Quad q = w>>2 owns K-half [q*512, q*512+512), its own
// 2-stage cp.async ring + named barrier (1+q). Warp in quad mt = w&3 computes
// m16 (batches mt*16..) x n32 (ALL gate cols): per k16 -> 2 A-LDSM.x4 + 4 B-LDSM.x4,
// 12 MMAs into 3 split-term accumulators x 4 n-tiles. Partial K-sums merged via
// two smem pre arrays, then pointwise cell in threads 0-63.
#define KC 128
// smem: swizzled, pitch 256 B/row (128 bf16). SWZ XORs the 16B segment with row&7.
#define SWZ(row, seg) ((unsigned)((row) * 256 + ((((seg) ^ ((row) & 7))) << 4)))
#define H_PL 16384               // 64 rows x 256
#define W_PL 8192                // 32 rows x 256
#define STG_BYTES (2 * H_PL + 2 * W_PL)   // 49152: h hi, h lo, w hi, w lo
#define OFF_WQ (2 * STG_BYTES)            // per-quad region = 2 stages
#define OFF_PRE (2 * OFF_WQ)              // 196608
#define PRE_SZ (64 * 36 * 4)              // 9216
#define SMEM_BYTES (OFF_PRE + 2 * PRE_SZ) // 215040

__global__ __launch_bounds__(256) void lstm_step_mma(
    const int* __restrict__ lens, float* __restrict__ out, int t) {
    extern __shared__ unsigned char smem[];
    const uint32_t sb = smem_u32(smem);
    float* pre0 = (float*)(smem + OFF_PRE);
    float* pre1 = (float*)(smem + OFF_PRE + PRE_SZ);

    const int tid = threadIdx.x;
    const int lane = tid & 31;
    const int w = tid >> 5;
    const int q = w >> 2;            // K-half
    const int mt = w & 3;            // m-tile
    const int tq = tid & 127;        // thread-in-quad
    const int jb = blockIdx.x;
    const int j0 = jb * 8;
    const int pp = t & 1;
    const uint32_t qbase = sb + q * OFF_WQ;
    const int barid = 1 + q;

    const __nv_bfloat16* hsrc = &g_h[pp][0][0][0];
    const __nv_bfloat16* wsrc = &g_W_img[jb][0][0][0];

    // ---- cp.async issuer: chunk kc (0..3) of this quad's K-half
    auto issue_chunk = [&](int kc) {
        uint32_t base = qbase + (kc & 1) * STG_BYTES;
        int koff = q * 512 + kc * KC;
#pragma unroll
        for (int r = 0; r < 16; r++) {        // h: 2048 ops / 128 thr
            int i = r * 128 + tq;
            int plane = i >> 10, rem = i & 1023;
            int row = rem >> 4, seg = rem & 15;
            const void* src = hsrc + ((size_t)plane * Bdim + row) * Hdim + koff + seg * 8;
            cp16(base + plane * H_PL + SWZ(row, seg), src);
        }
#pragma unroll
        for (int r = 0; r < 8; r++) {         // w: 1024 ops / 128 thr
            int i = r * 128 + tq;
            int plane = i >> 9, rem = i & 511;
            int row = rem >> 4, seg = rem & 15;
            const void* src = wsrc + ((size_t)plane * 32 + row) * Hdim + koff + seg * 8;
            cp16(base + 2 * H_PL + plane * W_PL + SWZ(row, seg), src);
        }
        cp_commit();
    };

    issue_chunk(0);

    // ---- tail-state prefetch (threads 0-63, b = tid)
    float gx[32], cst[8];
    int lb = 0;
    if (tid < 64) {
        const float* gxb = g_gates_x + ((size_t)t * Bdim + tid) * Gdim + j0;
#pragma unroll
        for (int g = 0; g < 4; g++) {
            float4 v0 = *(const float4*)(gxb + g * Hdim);
            float4 v1 = *(const float4*)(gxb + g * Hdim + 4);
            gx[g * 8 + 0] = v0.x; gx[g * 8 + 1] = v0.y; gx[g * 8 + 2] = v0.z; gx[g * 8 + 3] = v0.w;
            gx[g * 8 + 4] = v1.x; gx[g * 8 + 5] = v1.y; gx[g * 8 + 6] = v1.z; gx[g * 8 + 7] = v1.w;
        }
        float4 c0 = *(const float4*)&g_c[jb][tid][0];
        float4 c1 = *(const float4*)&g_c[jb][tid][4];
        cst[0] = c0.x; cst[1] = c0.y; cst[2] = c0.z; cst[3] = c0.w;
        cst[4] = c1.x; cst[5] = c1.y; cst[6] = c1.z; cst[7] = c1.w;
        lb = lens[tid];
    }

    // ---- per-lane fragment addressing (swizzled)
    const int rowa = mt * 16 + (lane & 7) + ((lane >> 3) & 1) * 8;   // A row (batch)
    const int selA = (lane >> 4) & 1;
    const int xa = rowa & 7;
    const uint32_t a_base = (uint32_t)(rowa * 256);
    const int rowb = (lane & 7) + ((lane >> 4) & 1) * 8;             // B row (gate col)
    const int selB = (lane >> 3) & 1;
    const int xb = rowb & 7;
    const uint32_t b_base = (uint32_t)(2 * H_PL + rowb * 256);

    float C0[4][4], C1[4][4], C2[4][4];
#pragma unroll
    for (int nt = 0; nt < 4; nt++)
#pragma unroll
        for (int k = 0; k < 4; k++) { C0[nt][k] = 0.f; C1[nt][k] = 0.f; C2[nt][k] = 0.f; }

    for (int kc = 0; kc < 4; kc++) {
        if (kc + 1 < 4) { issue_chunk(kc + 1); cp_wait<1>(); }
        else            { cp_wait<0>(); }
        barq(barid);                  // copies of chunk kc visible quad-wide

        uint32_t base = qbase + (kc & 1) * STG_BYTES;
#pragma unroll
        for (int ks = 0; ks < 8; ks++) {
            uint32_t aoff = base + a_base + (uint32_t)((((2 * ks + selA) ^ xa)) << 4);
            uint32_t boff = base + b_base + (uint32_t)((((2 * ks + selB) ^ xb)) << 4);
            uint32_t ah0, ah1, ah2, ah3, al0, al1, al2, al3;
            ldm_x4(ah0, ah1, ah2, ah3, aoff);
            ldm_x4(al0, al1, al2, al3, aoff + H_PL);
            uint32_t p0, p1, p2, p3, p4, p5, p6, p7;      // B hi n0-15, n16-31
            ldm_x4(p0, p1, p2, p3, boff);
            ldm_x4(p4, p5, p6, p7, boff + 4096);
            uint32_t s0, s1, s2, s3, s4, s5, s6, s7;      // B lo
            ldm_x4(s0, s1, s2, s3, boff + W_PL);
            ldm_x4(s4, s5, s6, s7, boff + W_PL + 4096);

            mma_bf16(C0[0], ah0, ah1, ah2, ah3, p0, p1);
            mma_bf16(C0[1], ah0, ah1, ah2, ah3, p2, p3);
            mma_bf16(C0[2], ah0, ah1, ah2, ah3, p4, p5);
            mma_bf16(C0[3], ah0, ah1, ah2, ah3, p6, p7);
            mma_bf16(C1[0], ah0, ah1, ah2, ah3, s0, s1);
            mma_bf16(C1[1], ah0, ah1, ah2, ah3, s2, s3);
            mma_bf16(C1[2], ah0, ah1, ah2, ah3, s4, s5);
            mma_bf16(C1[3], ah0, ah1, ah2, ah3, s6, s7);
            mma_bf16(C2[0], al0, al1, al2, al3, p0, p1);
            mma_bf16(C2[1], al0, al1, al2, al3, p2, p3);
            mma_bf16(C2[2], al0, al1, al2, al3, p4, p5);
            mma_bf16(C2[3], al0, al1, al2, al3, p6, p7);
        }
        barq(barid);                  // all reads of buffer kc&1 done before next issue
    }

    // ---- stage per-quad partial sums -> pre_q[64][36]
    {
        float* preq = q ? pre1 : pre0;
        int g = lane >> 2, t2 = (lane & 3) * 2;
        int m = mt * 16 + g;
#pragma unroll
        for (int nt = 0; nt < 4; nt++) {
            float s0 = C0[nt][0] + C1[nt][0] + C2[nt][0];
            float s1 = C0[nt][1] + C1[nt][1] + C2[nt][1];
            float s2 = C0[nt][2] + C1[nt][2] + C2[nt][2];
            float s3 = C0[nt][3] + C1[nt][3] + C2[nt][3];
            int n = nt * 8 + t2;
            *(float2*)&preq[m * 36 + n]       = make_float2(s0, s1);
            *(float2*)&preq[(m + 8) * 36 + n] = make_float2(s2, s3);
        }
    }
    __syncthreads();

    // ---- pointwise LSTM cell (threads 0-63, b = tid)
    if (tid < 64) {
        int b = tid;
        float hn[8];
        unsigned short hu[8], lu[8];
#pragma unroll
        for (int jj = 0; jj < 8; jj++) {
            float xi = pre0[b * 36 + jj]      + pre1[b * 36 + jj]      + gx[jj];
            float xf = pre0[b * 36 + 8 + jj]  + pre1[b * 36 + 8 + jj]  + gx[8 + jj];
            float xg = pre0[b * 36 + 16 + jj] + pre1[b * 36 + 16 + jj] + gx[16 + jj];
            float xo = pre0[b * 36 + 24 + jj] + pre1[b * 36 + 24 + jj] + gx[24 + jj];
            float i_ = sigm_(xi), f_ = sigm_(xf), g_ = tanh_(xg), o_ = sigm_(xo);
            float cn = f_ * cst[jj] + i_ * g_;
            cst[jj] = cn;
            float h = o_ * tanh_(cn);
            hn[jj] = h;
            __nv_bfloat16 hh = __float2bfloat16(h);
            __nv_bfloat16 hl = __float2bfloat16(h - __bfloat162float(hh));
            hu[jj] = __bfloat16_as_ushort(hh);
            lu[jj] = __bfloat16_as_ushort(hl);
        }
        *(float4*)&g_c[jb][b][0] = make_float4(cst[0], cst[1], cst[2], cst[3]);
        *(float4*)&g_c[jb][b][4] = make_float4(cst[4], cst[5], cst[6], cst[7]);

        uint4 vh, vl;
        vh.x = (uint32_t)hu[0] | ((uint32_t)hu[1] << 16);
        vh.y = (uint32_t)hu[2] | ((uint32_t)hu[3] << 16);
        vh.z = (uint32_t)hu[4] | ((uint32_t)hu[5] << 16);
        vh.w = (uint32_t)hu[6] | ((uint32_t)hu[7] << 16);
        vl.x = (uint32_t)lu[0] | ((uint32_t)lu[1] << 16);
        vl.y = (uint32_t)lu[2] | ((uint32_t)lu[3] << 16);
        vl.z = (uint32_t)lu[4] | ((uint32_t)lu[5] << 16);
        vl.w = (uint32_t)lu[6] | ((uint32_t)lu[7] << 16);
        int pp1 = pp ^ 1;
        *(uint4*)&g_h[pp1][0][b][j0] = vh;
        *(uint4*)&g_h[pp1][1][b][j0] = vl;

        if (lb > t) {
            float* ob = out + (size_t)b * Hdim + j0;
            *(float4*)(ob)     = make_float4(hn[0], hn[1], hn[2], hn[3]);
            *(float4*)(ob + 4) = make_float4(hn[4], hn[5], hn[6], hn[7]);
        }
    }
}

// ---------------- launch ------------------------------------------------------------
extern "C" void kernel_launch(void* const* d_in, const int* in_sizes, int n_in,
                              void* d_out, int out_size) {
    const float* seq   = (const float*)d_in[0];
    const int*   lensp = (const int*)d_in[1];
    const float* Wih   = (const float*)d_in[2];
    const float* Whh   = (const float*)d_in[3];
    const float* bih   = (const float*)d_in[4];
    const float* bhh   = (const float*)d_in[5];
    float* out = (float*)d_out;

    cudaFuncSetAttribute(lstm_step_mma,
                         cudaFuncAttributeMaxDynamicSharedMemorySize, SMEM_BYTES);

    init_state<<<256, 256>>>(out);
    w_prep<<<4096, 256>>>(Whh);

    dim3 g1(Gdim / 128, (Bdim * Tdim) / 128);
    gates_x_gemm<<<g1, 256>>>(seq, Wih, bih, bhh);

    for (int t = 0; t < Tdim; t++) {
        lstm_step_mma<<<NCTA, 256, SMEM_BYTES>>>(lensp, out, t);
    }
}